// round 8
// baseline (speedup 1.0000x reference)
#include <cuda_runtime.h>
#include <stdint.h>
#include <math.h>

// ---------------- problem constants ----------------
#define MDIM 16384      // B*S
#define NDIM 2048       // F
#define KDIM 2048       // D
#define TM   128        // CTA tile M
#define TN   128        // CTA tile N
#define TKC  64         // K bytes per pipeline stage (2 k32 MMA steps)
#define KITERS (KDIM/TKC)   // 32
#define EPSV 1e-6f
#define QMAX 32600.0f   // fixed-point full scale (keeps hi,lo in int8 range)

// SMEM per stage: Ah | Al | Bh | Bl, each 128 rows x 64 bytes, padded to 80B rows
#define ROWB   80
#define AH_OFF 0
#define AL_OFF (128*ROWB)        // 10240
#define BH_OFF (2*128*ROWB)      // 20480
#define BL_OFF (3*128*ROWB)      // 30720
#define STAGE_BYTES (4*128*ROWB) // 40960
#define NSTAGE 3
#define SMEM_BYTES (NSTAGE*STAGE_BYTES)   // 122880

// ---------------- scratch ----------------
__device__ int8_t g_x_hi[33554432];
__device__ int8_t g_x_lo[33554432];
__device__ int8_t g_w_hi[4194304];
__device__ int8_t g_w_lo[4194304];
__device__ float  g_x_sq[MDIM];
__device__ float  g_w_sq[NDIM];
__device__ float  g_x_sc[MDIM];
__device__ float  g_w_sc[NDIM];

// ---------------- PTX helpers ----------------
__device__ __forceinline__ uint32_t smem_u32(const void* p) {
    uint32_t r;
    asm("{ .reg .u64 t; cvta.to.shared.u64 t, %1; cvt.u32.u64 %0, t; }" : "=r"(r) : "l"(p));
    return r;
}
__device__ __forceinline__ void cp16(uint32_t dst, const void* src) {
    asm volatile("cp.async.cg.shared.global [%0], [%1], 16;" :: "r"(dst), "l"(src) : "memory");
}
__device__ __forceinline__ void cp_commit() {
    asm volatile("cp.async.commit_group;" ::: "memory");
}
template <int N>
__device__ __forceinline__ void cp_wait() {
    asm volatile("cp.async.wait_group %0;" :: "n"(N) : "memory");
}
__device__ __forceinline__ void ldsm4(uint32_t* r, uint32_t addr) {
    asm volatile("ldmatrix.sync.aligned.m8n8.x4.shared.b16 {%0,%1,%2,%3}, [%4];"
        : "=r"(r[0]), "=r"(r[1]), "=r"(r[2]), "=r"(r[3]) : "r"(addr));
}
// m16n8k32 int8 MMA, s32 accumulate
__device__ __forceinline__ void imma(int* c, const uint32_t* a, uint32_t b0, uint32_t b1) {
    asm volatile(
        "mma.sync.aligned.m16n8k32.row.col.s32.s8.s8.s32 "
        "{%0,%1,%2,%3}, {%4,%5,%6,%7}, {%8,%9}, {%0,%1,%2,%3};"
        : "+r"(c[0]), "+r"(c[1]), "+r"(c[2]), "+r"(c[3])
        : "r"(a[0]), "r"(a[1]), "r"(a[2]), "r"(a[3]), "r"(b0), "r"(b1));
}

// ---------------- pre-pass: fp32 -> 16-bit fixed point (hi,lo int8 planes) ----
// + per-row scale + per-row exact sum of squares
__global__ __launch_bounds__(256) void quant_kernel(const float* __restrict__ x,
                                                    const float* __restrict__ w) {
    int row = blockIdx.x;
    const float* src;
    int8_t *hi, *lo;
    float *sq, *sc;
    if (row < MDIM) {
        src = x + (size_t)row * KDIM;
        hi = g_x_hi + (size_t)row * KDIM;
        lo = g_x_lo + (size_t)row * KDIM;
        sq = g_x_sq + row;  sc = g_x_sc + row;
    } else {
        int r = row - MDIM;
        src = w + (size_t)r * KDIM;
        hi = g_w_hi + (size_t)r * KDIM;
        lo = g_w_lo + (size_t)r * KDIM;
        sq = g_w_sq + r;  sc = g_w_sc + r;
    }
    const int tid = threadIdx.x;
    float4 v0 = *reinterpret_cast<const float4*>(src + tid * 4);
    float4 v1 = *reinterpret_cast<const float4*>(src + tid * 4 + 1024);

    float acc = v0.x*v0.x + v0.y*v0.y + v0.z*v0.z + v0.w*v0.w
              + v1.x*v1.x + v1.y*v1.y + v1.z*v1.z + v1.w*v1.w;
    float mx = fmaxf(fmaxf(fmaxf(fabsf(v0.x), fabsf(v0.y)), fmaxf(fabsf(v0.z), fabsf(v0.w))),
                     fmaxf(fmaxf(fabsf(v1.x), fabsf(v1.y)), fmaxf(fabsf(v1.z), fabsf(v1.w))));

    __shared__ float rsum[8], rmax[8], bmax;
    #pragma unroll
    for (int o = 16; o > 0; o >>= 1) {
        acc += __shfl_xor_sync(0xffffffffu, acc, o);
        mx = fmaxf(mx, __shfl_xor_sync(0xffffffffu, mx, o));
    }
    if ((tid & 31) == 0) { rsum[tid >> 5] = acc; rmax[tid >> 5] = mx; }
    __syncthreads();
    if (tid < 8) {
        float s = rsum[tid], m = rmax[tid];
        #pragma unroll
        for (int o = 4; o > 0; o >>= 1) {
            s += __shfl_xor_sync(0xffu, s, o);
            m = fmaxf(m, __shfl_xor_sync(0xffu, m, o));
        }
        if (tid == 0) { *sq = s; *sc = m / QMAX; bmax = m; }
    }
    __syncthreads();
    const float maxv = bmax;
    const float inv = (maxv > 0.f) ? (QMAX / maxv) : 0.f;

    uint32_t ph[2], pl[2];
    const float* vv = &v0.x;
    #pragma unroll
    for (int half = 0; half < 2; half++) {
        uint32_t wh = 0, wl = 0;
        #pragma unroll
        for (int e = 0; e < 4; e++) {
            float f = (half == 0) ? vv[e] : (&v1.x)[e];
            int q = __float2int_rn(f * inv);
            int h = (q + 128) >> 8;
            int l = q - (h << 8);
            wh |= ((uint32_t)(uint8_t)(int8_t)h) << (8 * e);
            wl |= ((uint32_t)(uint8_t)(int8_t)l) << (8 * e);
        }
        ph[half] = wh; pl[half] = wl;
    }
    reinterpret_cast<uint32_t*>(hi)[tid]       = ph[0];
    reinterpret_cast<uint32_t*>(lo)[tid]       = pl[0];
    reinterpret_cast<uint32_t*>(hi)[tid + 256] = ph[1];
    reinterpret_cast<uint32_t*>(lo)[tid + 256] = pl[1];
}

// ---------------- main GEMM + Yat epilogue ----------------
// grid = (MDIM/TM)*(NDIM/TN) = 128*16 = 2048, block = 256 (8 warps: 2 M x 4 N),
// warp tile 64x32, 3-stage cp.async pipeline, 1 barrier per k-iter.
__global__ __launch_bounds__(256, 1) void yat_gemm(float* __restrict__ out,
                                                   const float* __restrict__ alpha,
                                                   const float* __restrict__ bias) {
    extern __shared__ char smem[];
    const uint32_t smem_base = smem_u32(smem);

    const int tid = threadIdx.x;
    const int mtile = blockIdx.x >> 4;
    const int ntile = blockIdx.x & 15;
    const int m0 = mtile * TM;
    const int n0 = ntile * TN;

    const int8_t* xh = g_x_hi + (size_t)m0 * KDIM;
    const int8_t* xl = g_x_lo + (size_t)m0 * KDIM;
    const int8_t* wh = g_w_hi + (size_t)n0 * KDIM;
    const int8_t* wl = g_w_lo + (size_t)n0 * KDIM;

    // ---- stage loader: 4 mats x 128 rows x 64B = 2048B rows -> 512 chunks/mat ----
    auto load_stage = [&](int i) {
        const uint32_t sb = smem_base + (uint32_t)(i % NSTAGE) * STAGE_BYTES;
        const int kk = i * TKC;
        #pragma unroll
        for (int half = 0; half < 2; half++) {
            int q = tid + 256 * half;
            int r = q >> 2, c = q & 3;
            uint32_t so = (uint32_t)r * ROWB + (uint32_t)c * 16;
            size_t go = (size_t)r * KDIM + kk + c * 16;
            cp16(sb + AH_OFF + so, xh + go);
            cp16(sb + AL_OFF + so, xl + go);
            cp16(sb + BH_OFF + so, wh + go);
            cp16(sb + BL_OFF + so, wl + go);
        }
    };

    // ---- warp/lane geometry ----
    const int warp = tid >> 5;
    const int lane = tid & 31;
    const int wm = warp & 1;        // 2 warps along M (64 rows each)
    const int wn = warp >> 1;       // 4 warps along N (32 cols each)

    // ldmatrix per-lane offsets (identical structure to f16; bytes instead of halves)
    const uint32_t a_loff = (uint32_t)(wm * 64 + (lane & 15)) * ROWB
                          + (uint32_t)(lane >> 4) * 16;
    const uint32_t b_loff = (uint32_t)(wn * 32 + (lane & 7) + ((lane >> 4) & 1) * 8) * ROWB
                          + (uint32_t)((lane >> 3) & 1) * 16;

    int acch[4][4][4];   // hi*hi   (weight 65536)
    int accm[4][4][4];   // hi*lo + lo*hi (weight 256)
    #pragma unroll
    for (int mi = 0; mi < 4; mi++)
        #pragma unroll
        for (int ni = 0; ni < 4; ni++)
            #pragma unroll
            for (int e = 0; e < 4; e++) { acch[mi][ni][e] = 0; accm[mi][ni][e] = 0; }

    load_stage(0); cp_commit();
    load_stage(1); cp_commit();

    for (int i = 0; i < KITERS; i++) {
        if (i == KITERS - 1) cp_wait<0>(); else cp_wait<1>();
        __syncthreads();
        if (i + 2 < KITERS) { load_stage(i + 2); cp_commit(); }

        const uint32_t sb = smem_base + (uint32_t)(i % NSTAGE) * STAGE_BYTES;
        const uint32_t aAh = sb + AH_OFF + a_loff;
        const uint32_t aAl = sb + AL_OFF + a_loff;
        const uint32_t aBh = sb + BH_OFF + b_loff;
        const uint32_t aBl = sb + BL_OFF + b_loff;

        #pragma unroll
        for (int ks = 0; ks < 2; ks++) {
            const uint32_t kb = (uint32_t)ks * 32;
            uint32_t bh[2][4];
            ldsm4(bh[0], aBh + kb);
            ldsm4(bh[1], aBh + 16 * ROWB + kb);
            uint32_t ah[4][4];
            #pragma unroll
            for (int mi = 0; mi < 4; mi++)
                ldsm4(ah[mi], aAh + (uint32_t)mi * (16 * ROWB) + kb);
            #pragma unroll
            for (int ni = 0; ni < 4; ni++) {
                uint32_t b0 = bh[ni >> 1][(ni & 1) * 2];
                uint32_t b1 = bh[ni >> 1][(ni & 1) * 2 + 1];
                #pragma unroll
                for (int mi = 0; mi < 4; mi++)
                    imma(acch[mi][ni], ah[mi], b0, b1);        // hi*hi
            }
            uint32_t bl[2][4];
            ldsm4(bl[0], aBl + kb);
            ldsm4(bl[1], aBl + 16 * ROWB + kb);
            #pragma unroll
            for (int ni = 0; ni < 4; ni++) {
                uint32_t b0 = bl[ni >> 1][(ni & 1) * 2];
                uint32_t b1 = bl[ni >> 1][(ni & 1) * 2 + 1];
                #pragma unroll
                for (int mi = 0; mi < 4; mi++)
                    imma(accm[mi][ni], ah[mi], b0, b1);        // hi*lo
            }
            uint32_t al[4][4];
            #pragma unroll
            for (int mi = 0; mi < 4; mi++)
                ldsm4(al[mi], aAl + (uint32_t)mi * (16 * ROWB) + kb);
            #pragma unroll
            for (int ni = 0; ni < 4; ni++) {
                uint32_t b0 = bh[ni >> 1][(ni & 1) * 2];
                uint32_t b1 = bh[ni >> 1][(ni & 1) * 2 + 1];
                #pragma unroll
                for (int mi = 0; mi < 4; mi++)
                    imma(accm[mi][ni], al[mi], b0, b1);        // lo*hi
            }
        }
    }

    // ---- epilogue: reconstruct y and apply Yat transform ----
    const int g  = lane >> 2;
    const int tg = lane & 3;
    const float a = *alpha;
    const float basev = sqrtf((float)NDIM) / logf(1.0f + (float)NDIM);
    const float scale = powf(basev, a);

    #pragma unroll
    for (int mi = 0; mi < 4; mi++) {
        const int r0 = m0 + wm * 64 + mi * 16 + g;
        const float xs0 = g_x_sq[r0];
        const float xs1 = g_x_sq[r0 + 8];
        const float sx0 = g_x_sc[r0];
        const float sx1 = g_x_sc[r0 + 8];
        #pragma unroll
        for (int ni = 0; ni < 4; ni++) {
            const int col = n0 + wn * 32 + ni * 8 + tg * 2;
            const float ws0 = __ldg(&g_w_sq[col]);
            const float ws1 = __ldg(&g_w_sq[col + 1]);
            const float sw0 = __ldg(&g_w_sc[col]);
            const float sw1 = __ldg(&g_w_sc[col + 1]);
            const float bi0 = __ldg(&bias[col]);
            const float bi1 = __ldg(&bias[col + 1]);
            float y;
            float2 o;
            y = sx0 * sw0 * fmaf(65536.f, (float)acch[mi][ni][0], 256.f * (float)accm[mi][ni][0]);
            o.x = scale * y * y / (xs0 + ws0 - 2.0f * y + EPSV) + bi0;
            y = sx0 * sw1 * fmaf(65536.f, (float)acch[mi][ni][1], 256.f * (float)accm[mi][ni][1]);
            o.y = scale * y * y / (xs0 + ws1 - 2.0f * y + EPSV) + bi1;
            *reinterpret_cast<float2*>(out + (size_t)r0 * NDIM + col) = o;
            y = sx1 * sw0 * fmaf(65536.f, (float)acch[mi][ni][2], 256.f * (float)accm[mi][ni][2]);
            o.x = scale * y * y / (xs1 + ws0 - 2.0f * y + EPSV) + bi0;
            y = sx1 * sw1 * fmaf(65536.f, (float)acch[mi][ni][3], 256.f * (float)accm[mi][ni][3]);
            o.y = scale * y * y / (xs1 + ws1 - 2.0f * y + EPSV) + bi1;
            *reinterpret_cast<float2*>(out + (size_t)(r0 + 8) * NDIM + col) = o;
        }
    }
}

// ---------------- launch ----------------
extern "C" void kernel_launch(void* const* d_in, const int* in_sizes, int n_in,
                              void* d_out, int out_size) {
    (void)in_sizes; (void)n_in; (void)out_size;
    const float* x     = (const float*)d_in[0];
    const float* w     = (const float*)d_in[1];
    const float* alpha = (const float*)d_in[2];
    const float* bias  = (const float*)d_in[3];
    float* out = (float*)d_out;

    cudaFuncSetAttribute(yat_gemm, cudaFuncAttributeMaxDynamicSharedMemorySize, SMEM_BYTES);

    quant_kernel<<<MDIM + NDIM, 256>>>(x, w);
    yat_gemm<<<(MDIM / TM) * (NDIM / TN), 256, SMEM_BYTES>>>(out, alpha, bias);
}

// round 9
// speedup vs baseline: 2.5681x; 2.5681x over previous
#include <cuda_runtime.h>
#include <cuda_fp16.h>
#include <stdint.h>
#include <math.h>

// ---------------- problem constants ----------------
#define MDIM 16384      // B*S
#define NDIM 2048       // F
#define KDIM 2048       // D
#define TM   128        // CTA tile M
#define TN   128        // CTA tile N
#define TKC  32         // K (halves) per pipeline stage
#define KITERS (KDIM/TKC)   // 64
#define EPSV 1e-6f

// SMEM per stage: A (x fp16) | Bh (w_hi) | Bl (w_lo); 128 rows x 64B, padded to 80B
#define ROWB   80
#define A_OFF  0
#define BH_OFF (128*ROWB)        // 10240
#define BL_OFF (2*128*ROWB)      // 20480
#define STAGE_BYTES (3*128*ROWB) // 30720
#define NSTAGE 3
#define SMEM_BYTES (NSTAGE*STAGE_BYTES)   // 92160 -> 2 CTAs/SM

// ---------------- scratch ----------------
__device__ __half g_x_h[33554432];
__device__ __half g_w_h[4194304];
__device__ __half g_w_l[4194304];
__device__ float  g_x_sq[MDIM];
__device__ float  g_w_sq[NDIM];

// ---------------- PTX helpers ----------------
__device__ __forceinline__ uint32_t smem_u32(const void* p) {
    uint32_t r;
    asm("{ .reg .u64 t; cvta.to.shared.u64 t, %1; cvt.u32.u64 %0, t; }" : "=r"(r) : "l"(p));
    return r;
}
__device__ __forceinline__ void cp16(uint32_t dst, const void* src) {
    asm volatile("cp.async.cg.shared.global [%0], [%1], 16;" :: "r"(dst), "l"(src) : "memory");
}
__device__ __forceinline__ void cp_commit() {
    asm volatile("cp.async.commit_group;" ::: "memory");
}
template <int N>
__device__ __forceinline__ void cp_wait() {
    asm volatile("cp.async.wait_group %0;" :: "n"(N) : "memory");
}
__device__ __forceinline__ void ldsm4(uint32_t* r, uint32_t addr) {
    asm volatile("ldmatrix.sync.aligned.m8n8.x4.shared.b16 {%0,%1,%2,%3}, [%4];"
        : "=r"(r[0]), "=r"(r[1]), "=r"(r[2]), "=r"(r[3]) : "r"(addr));
}
// m16n8k16 row.col f16 -> f32
__device__ __forceinline__ void mma16816(float* c, const uint32_t* a, uint32_t b0, uint32_t b1) {
    asm volatile(
        "mma.sync.aligned.m16n8k16.row.col.f32.f16.f16.f32 "
        "{%0,%1,%2,%3}, {%4,%5,%6,%7}, {%8,%9}, {%0,%1,%2,%3};"
        : "+f"(c[0]), "+f"(c[1]), "+f"(c[2]), "+f"(c[3])
        : "r"(a[0]), "r"(a[1]), "r"(a[2]), "r"(a[3]), "r"(b0), "r"(b1));
}

// ---------------- pre-pass ----------------
// x rows: fp16(x) + exact row sum-of-squares.  w rows: fp16 hi/lo split + sum-of-squares.
__global__ __launch_bounds__(256) void split_kernel(const float* __restrict__ x,
                                                    const float* __restrict__ w) {
    int row = blockIdx.x;
    const int tid = threadIdx.x;
    float acc = 0.f;
    if (row < MDIM) {
        const float* src = x + (size_t)row * KDIM;
        __half* hi = g_x_h + (size_t)row * KDIM;
        #pragma unroll
        for (int half = 0; half < 2; half++) {
            int j = tid * 4 + half * 1024;
            float4 v = *reinterpret_cast<const float4*>(src + j);
            __half h0 = __float2half_rn(v.x), h1 = __float2half_rn(v.y);
            __half h2 = __float2half_rn(v.z), h3 = __float2half_rn(v.w);
            *reinterpret_cast<__half2*>(hi + j)     = __halves2half2(h0, h1);
            *reinterpret_cast<__half2*>(hi + j + 2) = __halves2half2(h2, h3);
            acc += v.x*v.x + v.y*v.y + v.z*v.z + v.w*v.w;
        }
        #pragma unroll
        for (int o = 16; o > 0; o >>= 1) acc += __shfl_xor_sync(0xffffffffu, acc, o);
        __shared__ float red[8];
        if ((tid & 31) == 0) red[tid >> 5] = acc;
        __syncthreads();
        if (tid < 8) {
            float v = red[tid];
            #pragma unroll
            for (int o = 4; o > 0; o >>= 1) v += __shfl_xor_sync(0xffu, v, o);
            if (tid == 0) g_x_sq[row] = v;
        }
    } else {
        int r = row - MDIM;
        const float* src = w + (size_t)r * KDIM;
        __half* hi = g_w_h + (size_t)r * KDIM;
        __half* lo = g_w_l + (size_t)r * KDIM;
        #pragma unroll
        for (int half = 0; half < 2; half++) {
            int j = tid * 4 + half * 1024;
            float4 v = *reinterpret_cast<const float4*>(src + j);
            __half h0 = __float2half_rn(v.x), h1 = __float2half_rn(v.y);
            __half h2 = __float2half_rn(v.z), h3 = __float2half_rn(v.w);
            __half l0 = __float2half_rn(v.x - __half2float(h0));
            __half l1 = __float2half_rn(v.y - __half2float(h1));
            __half l2 = __float2half_rn(v.z - __half2float(h2));
            __half l3 = __float2half_rn(v.w - __half2float(h3));
            *reinterpret_cast<__half2*>(hi + j)     = __halves2half2(h0, h1);
            *reinterpret_cast<__half2*>(hi + j + 2) = __halves2half2(h2, h3);
            *reinterpret_cast<__half2*>(lo + j)     = __halves2half2(l0, l1);
            *reinterpret_cast<__half2*>(lo + j + 2) = __halves2half2(l2, l3);
            acc += v.x*v.x + v.y*v.y + v.z*v.z + v.w*v.w;
        }
        #pragma unroll
        for (int o = 16; o > 0; o >>= 1) acc += __shfl_xor_sync(0xffffffffu, acc, o);
        __shared__ float red[8];
        if ((tid & 31) == 0) red[tid >> 5] = acc;
        __syncthreads();
        if (tid < 8) {
            float v = red[tid];
            #pragma unroll
            for (int o = 4; o > 0; o >>= 1) v += __shfl_xor_sync(0xffu, v, o);
            if (tid == 0) g_w_sq[r] = v;
        }
    }
}

// ---------------- main GEMM + Yat epilogue ----------------
// grid = 2048 (128 mtiles x 16 ntiles), block = 256 (8 warps: 2 M x 4 N, warp tile 64x32)
// 2-pass: y = sum x*w_hi + sum x*w_lo, single fp32 accumulator set.
// 3-stage cp.async pipeline, one __syncthreads per k-iter, 2 CTAs/SM.
__global__ __launch_bounds__(256, 2) void yat_gemm(float* __restrict__ out,
                                                   const float* __restrict__ alpha,
                                                   const float* __restrict__ bias) {
    extern __shared__ char smem[];
    const uint32_t smem_base = smem_u32(smem);

    const int tid = threadIdx.x;
    const int mtile = blockIdx.x >> 4;
    const int ntile = blockIdx.x & 15;
    const int m0 = mtile * TM;
    const int n0 = ntile * TN;

    const __half* xh = g_x_h + (size_t)m0 * KDIM;
    const __half* wh = g_w_h + (size_t)n0 * KDIM;
    const __half* wl = g_w_l + (size_t)n0 * KDIM;

    // ---- stage loader: 3 planes x 128 rows x 64B = 512 chunks/plane, 6 cp/thread ----
    auto load_stage = [&](int i) {
        const uint32_t sb = smem_base + (uint32_t)(i % NSTAGE) * STAGE_BYTES;
        const int kk = i * TKC;
        #pragma unroll
        for (int half = 0; half < 2; half++) {
            int q = tid + 256 * half;
            int r = q >> 2, c = q & 3;
            uint32_t so = (uint32_t)r * ROWB + (uint32_t)c * 16;
            size_t go = (size_t)r * KDIM + kk + c * 8;
            cp16(sb + A_OFF  + so, xh + go);
            cp16(sb + BH_OFF + so, wh + go);
            cp16(sb + BL_OFF + so, wl + go);
        }
    };

    // ---- warp/lane geometry ----
    const int warp = tid >> 5;
    const int lane = tid & 31;
    const int wm = warp & 1;        // 2 warps along M (64 rows each)
    const int wn = warp >> 1;       // 4 warps along N (32 cols each)

    const uint32_t a_loff = (uint32_t)(wm * 64 + (lane & 15)) * ROWB
                          + (uint32_t)(lane >> 4) * 16;
    const uint32_t b_loff = (uint32_t)(wn * 32 + (lane & 7) + ((lane >> 4) & 1) * 8) * ROWB
                          + (uint32_t)((lane >> 3) & 1) * 16;

    float acc[4][4][4];
    #pragma unroll
    for (int mi = 0; mi < 4; mi++)
        #pragma unroll
        for (int ni = 0; ni < 4; ni++)
            #pragma unroll
            for (int e = 0; e < 4; e++) acc[mi][ni][e] = 0.f;

    load_stage(0); cp_commit();
    load_stage(1); cp_commit();

    for (int i = 0; i < KITERS; i++) {
        if (i == KITERS - 1) cp_wait<0>(); else cp_wait<1>();
        __syncthreads();
        if (i + 2 < KITERS) { load_stage(i + 2); cp_commit(); }

        const uint32_t sb = smem_base + (uint32_t)(i % NSTAGE) * STAGE_BYTES;
        const uint32_t aA  = sb + A_OFF  + a_loff;
        const uint32_t aBh = sb + BH_OFF + b_loff;
        const uint32_t aBl = sb + BL_OFF + b_loff;

        #pragma unroll
        for (int ks = 0; ks < 2; ks++) {
            const uint32_t kb = (uint32_t)ks * 32;    // 16 halves per k-step
            uint32_t Bh[2][4];
            ldsm4(Bh[0], aBh + kb);
            ldsm4(Bh[1], aBh + 16 * ROWB + kb);
            uint32_t Ax[4][4];
            #pragma unroll
            for (int mi = 0; mi < 4; mi++)
                ldsm4(Ax[mi], aA + (uint32_t)mi * (16 * ROWB) + kb);
            uint32_t Bl[2][4];
            ldsm4(Bl[0], aBl + kb);
            ldsm4(Bl[1], aBl + 16 * ROWB + kb);
            #pragma unroll
            for (int ni = 0; ni < 4; ni++) {
                uint32_t b0 = Bh[ni >> 1][(ni & 1) * 2];
                uint32_t b1 = Bh[ni >> 1][(ni & 1) * 2 + 1];
                #pragma unroll
                for (int mi = 0; mi < 4; mi++)
                    mma16816(acc[mi][ni], Ax[mi], b0, b1);     // x * w_hi
            }
            #pragma unroll
            for (int ni = 0; ni < 4; ni++) {
                uint32_t b0 = Bl[ni >> 1][(ni & 1) * 2];
                uint32_t b1 = Bl[ni >> 1][(ni & 1) * 2 + 1];
                #pragma unroll
                for (int mi = 0; mi < 4; mi++)
                    mma16816(acc[mi][ni], Ax[mi], b0, b1);     // x * w_lo
            }
        }
    }

    // ---- epilogue: Yat transform from register accumulators ----
    const int g  = lane >> 2;
    const int tg = lane & 3;
    const float a = *alpha;
    const float basev = sqrtf((float)NDIM) / logf(1.0f + (float)NDIM);
    const float scale = powf(basev, a);

    #pragma unroll
    for (int mi = 0; mi < 4; mi++) {
        const int r0 = m0 + wm * 64 + mi * 16 + g;
        const float xs0 = g_x_sq[r0];
        const float xs1 = g_x_sq[r0 + 8];
        #pragma unroll
        for (int ni = 0; ni < 4; ni++) {
            const int col = n0 + wn * 32 + ni * 8 + tg * 2;
            const float ws0 = __ldg(&g_w_sq[col]);
            const float ws1 = __ldg(&g_w_sq[col + 1]);
            const float bi0 = __ldg(&bias[col]);
            const float bi1 = __ldg(&bias[col + 1]);
            float y;
            float2 o;
            y = acc[mi][ni][0];
            o.x = scale * y * y / (xs0 + ws0 - 2.0f * y + EPSV) + bi0;
            y = acc[mi][ni][1];
            o.y = scale * y * y / (xs0 + ws1 - 2.0f * y + EPSV) + bi1;
            *reinterpret_cast<float2*>(out + (size_t)r0 * NDIM + col) = o;
            y = acc[mi][ni][2];
            o.x = scale * y * y / (xs1 + ws0 - 2.0f * y + EPSV) + bi0;
            y = acc[mi][ni][3];
            o.y = scale * y * y / (xs1 + ws1 - 2.0f * y + EPSV) + bi1;
            *reinterpret_cast<float2*>(out + (size_t)(r0 + 8) * NDIM + col) = o;
        }
    }
}

// ---------------- launch ----------------
extern "C" void kernel_launch(void* const* d_in, const int* in_sizes, int n_in,
                              void* d_out, int out_size) {
    (void)in_sizes; (void)n_in; (void)out_size;
    const float* x     = (const float*)d_in[0];
    const float* w     = (const float*)d_in[1];
    const float* alpha = (const float*)d_in[2];
    const float* bias  = (const float*)d_in[3];
    float* out = (float*)d_out;

    cudaFuncSetAttribute(yat_gemm, cudaFuncAttributeMaxDynamicSharedMemorySize, SMEM_BYTES);

    split_kernel<<<MDIM + NDIM, 256>>>(x, w);
    yat_gemm<<<(MDIM / TM) * (NDIM / TN), 256, SMEM_BYTES>>>(out, alpha, bias);
}

// round 12
// speedup vs baseline: 3.6284x; 1.4129x over previous
#include <cuda_runtime.h>
#include <cuda_fp16.h>
#include <stdint.h>
#include <math.h>

// ---------------- problem constants ----------------
#define MDIM 16384      // B*S
#define NDIM 2048       // F
#define KDIM 2048       // D
#define TM   128        // CTA tile M
#define TN   128        // CTA tile N
#define TKC  64         // K (halves) per pipeline stage (4 k16 MMA steps)
#define KITERS (KDIM/TKC)   // 32
#define EPSV 1e-6f

// SMEM per stage: A (x fp16) | Bh (w_hi) | Bl (w_lo); 128 rows x 128B, padded to 144B
#define ROWB   144
#define A_OFF  0
#define BH_OFF (128*ROWB)        // 18432
#define BL_OFF (2*128*ROWB)      // 36864
#define STAGE_BYTES (3*128*ROWB) // 55296
#define NSTAGE 4
#define SMEM_BYTES (NSTAGE*STAGE_BYTES)   // 221184 -> 1 CTA/SM

// ---------------- scratch ----------------
__device__ __half g_x_h[33554432];
__device__ __half g_w_h[4194304];
__device__ __half g_w_l[4194304];
__device__ float  g_x_sq[MDIM];
__device__ float  g_w_sq[NDIM];

// ---------------- PTX helpers ----------------
__device__ __forceinline__ uint32_t smem_u32(const void* p) {
    uint32_t r;
    asm("{ .reg .u64 t; cvta.to.shared.u64 t, %1; cvt.u32.u64 %0, t; }" : "=r"(r) : "l"(p));
    return r;
}
__device__ __forceinline__ void cp16(uint32_t dst, const void* src) {
    asm volatile("cp.async.cg.shared.global [%0], [%1], 16;" :: "r"(dst), "l"(src) : "memory");
}
__device__ __forceinline__ void cp_commit() {
    asm volatile("cp.async.commit_group;" ::: "memory");
}
template <int N>
__device__ __forceinline__ void cp_wait() {
    asm volatile("cp.async.wait_group %0;" :: "n"(N) : "memory");
}
__device__ __forceinline__ void ldsm4(uint32_t* r, uint32_t addr) {
    asm volatile("ldmatrix.sync.aligned.m8n8.x4.shared.b16 {%0,%1,%2,%3}, [%4];"
        : "=r"(r[0]), "=r"(r[1]), "=r"(r[2]), "=r"(r[3]) : "r"(addr));
}
// m16n8k16 row.col f16 -> f32
__device__ __forceinline__ void mma16816(float* c, const uint32_t* a, uint32_t b0, uint32_t b1) {
    asm volatile(
        "mma.sync.aligned.m16n8k16.row.col.f32.f16.f16.f32 "
        "{%0,%1,%2,%3}, {%4,%5,%6,%7}, {%8,%9}, {%0,%1,%2,%3};"
        : "+f"(c[0]), "+f"(c[1]), "+f"(c[2]), "+f"(c[3])
        : "r"(a[0]), "r"(a[1]), "r"(a[2]), "r"(a[3]), "r"(b0), "r"(b1));
}

// ---------------- pre-pass ----------------
// x rows: fp16(x) + exact row sum-of-squares.  w rows: fp16 hi/lo split + sum-of-squares.
__global__ __launch_bounds__(256) void split_kernel(const float* __restrict__ x,
                                                    const float* __restrict__ w) {
    int row = blockIdx.x;
    const int tid = threadIdx.x;
    float acc = 0.f;
    __shared__ float red[8];
    if (row < MDIM) {
        const float* src = x + (size_t)row * KDIM;
        __half* hi = g_x_h + (size_t)row * KDIM;
        #pragma unroll
        for (int half = 0; half < 2; half++) {
            int j = tid * 4 + half * 1024;
            float4 v = *reinterpret_cast<const float4*>(src + j);
            __half h0 = __float2half_rn(v.x), h1 = __float2half_rn(v.y);
            __half h2 = __float2half_rn(v.z), h3 = __float2half_rn(v.w);
            *reinterpret_cast<__half2*>(hi + j)     = __halves2half2(h0, h1);
            *reinterpret_cast<__half2*>(hi + j + 2) = __halves2half2(h2, h3);
            acc += v.x*v.x + v.y*v.y + v.z*v.z + v.w*v.w;
        }
        #pragma unroll
        for (int o = 16; o > 0; o >>= 1) acc += __shfl_xor_sync(0xffffffffu, acc, o);
        if ((tid & 31) == 0) red[tid >> 5] = acc;
        __syncthreads();
        if (tid < 8) {
            float v = red[tid];
            #pragma unroll
            for (int o = 4; o > 0; o >>= 1) v += __shfl_xor_sync(0xffu, v, o);
            if (tid == 0) g_x_sq[row] = v;
        }
    } else {
        int r = row - MDIM;
        const float* src = w + (size_t)r * KDIM;
        __half* hi = g_w_h + (size_t)r * KDIM;
        __half* lo = g_w_l + (size_t)r * KDIM;
        #pragma unroll
        for (int half = 0; half < 2; half++) {
            int j = tid * 4 + half * 1024;
            float4 v = *reinterpret_cast<const float4*>(src + j);
            __half h0 = __float2half_rn(v.x), h1 = __float2half_rn(v.y);
            __half h2 = __float2half_rn(v.z), h3 = __float2half_rn(v.w);
            __half l0 = __float2half_rn(v.x - __half2float(h0));
            __half l1 = __float2half_rn(v.y - __half2float(h1));
            __half l2 = __float2half_rn(v.z - __half2float(h2));
            __half l3 = __float2half_rn(v.w - __half2float(h3));
            *reinterpret_cast<__half2*>(hi + j)     = __halves2half2(h0, h1);
            *reinterpret_cast<__half2*>(hi + j + 2) = __halves2half2(h2, h3);
            *reinterpret_cast<__half2*>(lo + j)     = __halves2half2(l0, l1);
            *reinterpret_cast<__half2*>(lo + j + 2) = __halves2half2(l2, l3);
            acc += v.x*v.x + v.y*v.y + v.z*v.z + v.w*v.w;
        }
        #pragma unroll
        for (int o = 16; o > 0; o >>= 1) acc += __shfl_xor_sync(0xffffffffu, acc, o);
        if ((tid & 31) == 0) red[tid >> 5] = acc;
        __syncthreads();
        if (tid < 8) {
            float v = red[tid];
            #pragma unroll
            for (int o = 4; o > 0; o >>= 1) v += __shfl_xor_sync(0xffu, v, o);
            if (tid == 0) g_w_sq[r] = v;
        }
    }
}

// ---------------- main GEMM + Yat epilogue ----------------
// grid = 2048 (128 mtiles x 16 ntiles), block = 256 (8 warps: 2 M x 4 N, warp tile 64x32)
// 2-pass: y = sum x*w_hi + sum x*w_lo, single fp32 accumulator set.
// TKC=64 halves -> 32 iterations, ONE barrier per iteration, 4-stage cp.async pipeline.
__global__ __launch_bounds__(256, 1) void yat_gemm(float* __restrict__ out,
                                                   const float* __restrict__ alpha,
                                                   const float* __restrict__ bias) {
    extern __shared__ char smem[];
    const uint32_t smem_base = smem_u32(smem);

    const int tid = threadIdx.x;
    const int mtile = blockIdx.x >> 4;
    const int ntile = blockIdx.x & 15;
    const int m0 = mtile * TM;
    const int n0 = ntile * TN;

    const __half* xh = g_x_h + (size_t)m0 * KDIM;
    const __half* wh = g_w_h + (size_t)n0 * KDIM;
    const __half* wl = g_w_l + (size_t)n0 * KDIM;

    // ---- stage loader: 3 planes x 128 rows x 128B = 1024 chunks/plane, 12 cp/thread ----
    auto load_stage = [&](int i) {
        const uint32_t sb = smem_base + (uint32_t)(i & 3) * STAGE_BYTES;
        const int kk = i * TKC;
        #pragma unroll
        for (int it = 0; it < 4; it++) {
            int q = tid + 256 * it;              // 0..1023
            int r = q >> 3, c = q & 7;
            uint32_t so = (uint32_t)r * ROWB + (uint32_t)c * 16;
            size_t go = (size_t)r * KDIM + kk + c * 8;
            cp16(sb + A_OFF  + so, xh + go);
            cp16(sb + BH_OFF + so, wh + go);
            cp16(sb + BL_OFF + so, wl + go);
        }
    };

    // ---- warp/lane geometry ----
    const int warp = tid >> 5;
    const int lane = tid & 31;
    const int wm = warp & 1;        // 2 warps along M (64 rows each)
    const int wn = warp >> 1;       // 4 warps along N (32 cols each)

    const uint32_t a_loff = (uint32_t)(wm * 64 + (lane & 15)) * ROWB
                          + (uint32_t)(lane >> 4) * 16;
    const uint32_t b_loff = (uint32_t)(wn * 32 + (lane & 7) + ((lane >> 4) & 1) * 8) * ROWB
                          + (uint32_t)((lane >> 3) & 1) * 16;

    float acc[4][4][4];
    #pragma unroll
    for (int mi = 0; mi < 4; mi++)
        #pragma unroll
        for (int ni = 0; ni < 4; ni++)
            #pragma unroll
            for (int e = 0; e < 4; e++) acc[mi][ni][e] = 0.f;

    load_stage(0); cp_commit();
    load_stage(1); cp_commit();
    load_stage(2); cp_commit();

    for (int i = 0; i < KITERS; i++) {
        if (i < KITERS - 3) cp_wait<2>(); else cp_wait<0>();
        __syncthreads();
        if (i + 3 < KITERS) { load_stage(i + 3); cp_commit(); }

        const uint32_t sb = smem_base + (uint32_t)(i & 3) * STAGE_BYTES;
        const uint32_t aA  = sb + A_OFF  + a_loff;
        const uint32_t aBh = sb + BH_OFF + b_loff;
        const uint32_t aBl = sb + BL_OFF + b_loff;

        #pragma unroll
        for (int ks = 0; ks < 4; ks++) {
            const uint32_t kb = (uint32_t)ks * 32;    // 16 halves per k-step
            uint32_t Bh[2][4];
            ldsm4(Bh[0], aBh + kb);
            ldsm4(Bh[1], aBh + 16 * ROWB + kb);
            uint32_t Ax[4][4];
            #pragma unroll
            for (int mi = 0; mi < 4; mi++)
                ldsm4(Ax[mi], aA + (uint32_t)mi * (16 * ROWB) + kb);
            uint32_t Bl[2][4];
            ldsm4(Bl[0], aBl + kb);
            ldsm4(Bl[1], aBl + 16 * ROWB + kb);
            #pragma unroll
            for (int ni = 0; ni < 4; ni++) {
                uint32_t b0 = Bh[ni >> 1][(ni & 1) * 2];
                uint32_t b1 = Bh[ni >> 1][(ni & 1) * 2 + 1];
                #pragma unroll
                for (int mi = 0; mi < 4; mi++)
                    mma16816(acc[mi][ni], Ax[mi], b0, b1);     // x * w_hi
            }
            #pragma unroll
            for (int ni = 0; ni < 4; ni++) {
                uint32_t b0 = Bl[ni >> 1][(ni & 1) * 2];
                uint32_t b1 = Bl[ni >> 1][(ni & 1) * 2 + 1];
                #pragma unroll
                for (int mi = 0; mi < 4; mi++)
                    mma16816(acc[mi][ni], Ax[mi], b0, b1);     // x * w_lo
            }
        }
    }

    // ---- epilogue: Yat transform from register accumulators ----
    const int g  = lane >> 2;
    const int tg = lane & 3;
    const float a = *alpha;
    const float basev = sqrtf((float)NDIM) / logf(1.0f + (float)NDIM);
    const float scale = powf(basev, a);

    #pragma unroll
    for (int mi = 0; mi < 4; mi++) {
        const int r0 = m0 + wm * 64 + mi * 16 + g;
        const float xs0 = g_x_sq[r0];
        const float xs1 = g_x_sq[r0 + 8];
        #pragma unroll
        for (int ni = 0; ni < 4; ni++) {
            const int col = n0 + wn * 32 + ni * 8 + tg * 2;
            const float ws0 = __ldg(&g_w_sq[col]);
            const float ws1 = __ldg(&g_w_sq[col + 1]);
            const float bi0 = __ldg(&bias[col]);
            const float bi1 = __ldg(&bias[col + 1]);
            float y;
            float2 o;
            y = acc[mi][ni][0];
            o.x = scale * y * y / (xs0 + ws0 - 2.0f * y + EPSV) + bi0;
            y = acc[mi][ni][1];
            o.y = scale * y * y / (xs0 + ws1 - 2.0f * y + EPSV) + bi1;
            *reinterpret_cast<float2*>(out + (size_t)r0 * NDIM + col) = o;
            y = acc[mi][ni][2];
            o.x = scale * y * y / (xs1 + ws0 - 2.0f * y + EPSV) + bi0;
            y = acc[mi][ni][3];
            o.y = scale * y * y / (xs1 + ws1 - 2.0f * y + EPSV) + bi1;
            *reinterpret_cast<float2*>(out + (size_t)(r0 + 8) * NDIM + col) = o;
        }
    }
}

// ---------------- launch ----------------
extern "C" void kernel_launch(void* const* d_in, const int* in_sizes, int n_in,
                              void* d_out, int out_size) {
    (void)in_sizes; (void)n_in; (void)out_size;
    const float* x     = (const float*)d_in[0];
    const float* w     = (const float*)d_in[1];
    const float* alpha = (const float*)d_in[2];
    const float* bias  = (const float*)d_in[3];
    float* out = (float*)d_out;

    cudaFuncSetAttribute(yat_gemm, cudaFuncAttributeMaxDynamicSharedMemorySize, SMEM_BYTES);

    split_kernel<<<MDIM + NDIM, 256>>>(x, w);
    yat_gemm<<<(MDIM / TM) * (NDIM / TN), 256, SMEM_BYTES>>>(out, alpha, bias);
}

// round 13
// speedup vs baseline: 4.7105x; 1.2982x over previous
#include <cuda_runtime.h>
#include <cuda_fp16.h>
#include <stdint.h>
#include <math.h>

// ---------------- problem constants ----------------
#define MDIM 16384      // B*S
#define NDIM 2048       // F
#define KDIM 2048       // D
#define TM   128        // CTA tile M
#define TN   128        // CTA tile N
#define TKC  64         // K (halves) per pipeline stage (4 k16 MMA steps)
#define KITERS (KDIM/TKC)   // 32
#define EPSV 1e-6f

// SMEM per stage: A (x fp16) | B (w fp16); 128 rows x 128B, padded to 144B
#define ROWB   144
#define A_OFF  0
#define B_OFF  (128*ROWB)        // 18432
#define STAGE_BYTES (2*128*ROWB) // 36864
#define NSTAGE 3
#define SMEM_BYTES (NSTAGE*STAGE_BYTES)   // 110592 -> 2 CTAs/SM

// ---------------- scratch ----------------
__device__ __half g_x_h[33554432];
__device__ __half g_w_h[4194304];
__device__ float  g_x_sq[MDIM];
__device__ float  g_w_sq[NDIM];

// ---------------- PTX helpers ----------------
__device__ __forceinline__ uint32_t smem_u32(const void* p) {
    uint32_t r;
    asm("{ .reg .u64 t; cvta.to.shared.u64 t, %1; cvt.u32.u64 %0, t; }" : "=r"(r) : "l"(p));
    return r;
}
__device__ __forceinline__ void cp16(uint32_t dst, const void* src) {
    asm volatile("cp.async.cg.shared.global [%0], [%1], 16;" :: "r"(dst), "l"(src) : "memory");
}
__device__ __forceinline__ void cp_commit() {
    asm volatile("cp.async.commit_group;" ::: "memory");
}
template <int N>
__device__ __forceinline__ void cp_wait() {
    asm volatile("cp.async.wait_group %0;" :: "n"(N) : "memory");
}
__device__ __forceinline__ void ldsm4(uint32_t* r, uint32_t addr) {
    asm volatile("ldmatrix.sync.aligned.m8n8.x4.shared.b16 {%0,%1,%2,%3}, [%4];"
        : "=r"(r[0]), "=r"(r[1]), "=r"(r[2]), "=r"(r[3]) : "r"(addr));
}
// m16n8k16 row.col f16 -> f32
__device__ __forceinline__ void mma16816(float* c, const uint32_t* a, uint32_t b0, uint32_t b1) {
    asm volatile(
        "mma.sync.aligned.m16n8k16.row.col.f32.f16.f16.f32 "
        "{%0,%1,%2,%3}, {%4,%5,%6,%7}, {%8,%9}, {%0,%1,%2,%3};"
        : "+f"(c[0]), "+f"(c[1]), "+f"(c[2]), "+f"(c[3])
        : "r"(a[0]), "r"(a[1]), "r"(a[2]), "r"(a[3]), "r"(b0), "r"(b1));
}

// ---------------- pre-pass: fp32 -> fp16 + exact row sum-of-squares ----------------
__global__ __launch_bounds__(256) void split_kernel(const float* __restrict__ x,
                                                    const float* __restrict__ w) {
    int row = blockIdx.x;
    const int tid = threadIdx.x;
    const float* src;
    __half* dst;
    float* sq;
    if (row < MDIM) {
        src = x + (size_t)row * KDIM;
        dst = g_x_h + (size_t)row * KDIM;
        sq = g_x_sq + row;
    } else {
        int r = row - MDIM;
        src = w + (size_t)r * KDIM;
        dst = g_w_h + (size_t)r * KDIM;
        sq = g_w_sq + r;
    }
    float acc = 0.f;
    #pragma unroll
    for (int half = 0; half < 2; half++) {
        int j = tid * 4 + half * 1024;
        float4 v = *reinterpret_cast<const float4*>(src + j);
        __half h0 = __float2half_rn(v.x), h1 = __float2half_rn(v.y);
        __half h2 = __float2half_rn(v.z), h3 = __float2half_rn(v.w);
        *reinterpret_cast<__half2*>(dst + j)     = __halves2half2(h0, h1);
        *reinterpret_cast<__half2*>(dst + j + 2) = __halves2half2(h2, h3);
        acc += v.x*v.x + v.y*v.y + v.z*v.z + v.w*v.w;
    }
    __shared__ float red[8];
    #pragma unroll
    for (int o = 16; o > 0; o >>= 1) acc += __shfl_xor_sync(0xffffffffu, acc, o);
    if ((tid & 31) == 0) red[tid >> 5] = acc;
    __syncthreads();
    if (tid < 8) {
        float v = red[tid];
        #pragma unroll
        for (int o = 4; o > 0; o >>= 1) v += __shfl_xor_sync(0xffu, v, o);
        if (tid == 0) *sq = v;
    }
}

// ---------------- main GEMM + Yat epilogue ----------------
// grid = 2048 (128 mtiles x 16 ntiles), block = 256 (8 warps: 2 M x 4 N, warp tile 64x32)
// single-pass fp16 x fp16 -> fp32 acc, TKC=64, 3-stage cp.async pipeline, 2 CTAs/SM.
__global__ __launch_bounds__(256, 2) void yat_gemm(float* __restrict__ out,
                                                   const float* __restrict__ alpha,
                                                   const float* __restrict__ bias) {
    extern __shared__ char smem[];
    const uint32_t smem_base = smem_u32(smem);

    const int tid = threadIdx.x;
    const int mtile = blockIdx.x >> 4;
    const int ntile = blockIdx.x & 15;
    const int m0 = mtile * TM;
    const int n0 = ntile * TN;

    const __half* xh = g_x_h + (size_t)m0 * KDIM;
    const __half* wh = g_w_h + (size_t)n0 * KDIM;

    // ---- stage loader: 2 planes x 128 rows x 128B = 1024 chunks/plane, 8 cp/thread ----
    auto load_stage = [&](int i) {
        const uint32_t sb = smem_base + (uint32_t)(i % NSTAGE) * STAGE_BYTES;
        const int kk = i * TKC;
        #pragma unroll
        for (int it = 0; it < 4; it++) {
            int q = tid + 256 * it;              // 0..1023
            int r = q >> 3, c = q & 7;
            uint32_t so = (uint32_t)r * ROWB + (uint32_t)c * 16;
            size_t go = (size_t)r * KDIM + kk + c * 8;
            cp16(sb + A_OFF + so, xh + go);
            cp16(sb + B_OFF + so, wh + go);
        }
    };

    // ---- warp/lane geometry ----
    const int warp = tid >> 5;
    const int lane = tid & 31;
    const int wm = warp & 1;        // 2 warps along M (64 rows each)
    const int wn = warp >> 1;       // 4 warps along N (32 cols each)

    const uint32_t a_loff = (uint32_t)(wm * 64 + (lane & 15)) * ROWB
                          + (uint32_t)(lane >> 4) * 16;
    const uint32_t b_loff = (uint32_t)(wn * 32 + (lane & 7) + ((lane >> 4) & 1) * 8) * ROWB
                          + (uint32_t)((lane >> 3) & 1) * 16;

    float acc[4][4][4];
    #pragma unroll
    for (int mi = 0; mi < 4; mi++)
        #pragma unroll
        for (int ni = 0; ni < 4; ni++)
            #pragma unroll
            for (int e = 0; e < 4; e++) acc[mi][ni][e] = 0.f;

    load_stage(0); cp_commit();
    load_stage(1); cp_commit();

    for (int i = 0; i < KITERS; i++) {
        if (i < KITERS - 2) cp_wait<1>(); else cp_wait<0>();
        __syncthreads();
        if (i + 2 < KITERS) { load_stage(i + 2); cp_commit(); }

        const uint32_t sb = smem_base + (uint32_t)(i % NSTAGE) * STAGE_BYTES;
        const uint32_t aA = sb + A_OFF + a_loff;
        const uint32_t aB = sb + B_OFF + b_loff;

        #pragma unroll
        for (int ks = 0; ks < 4; ks++) {
            const uint32_t kb = (uint32_t)ks * 32;    // 16 halves per k-step
            uint32_t Bf[2][4];
            ldsm4(Bf[0], aB + kb);
            ldsm4(Bf[1], aB + 16 * ROWB + kb);
            uint32_t Ax[4][4];
            #pragma unroll
            for (int mi = 0; mi < 4; mi++)
                ldsm4(Ax[mi], aA + (uint32_t)mi * (16 * ROWB) + kb);
            #pragma unroll
            for (int ni = 0; ni < 4; ni++) {
                uint32_t b0 = Bf[ni >> 1][(ni & 1) * 2];
                uint32_t b1 = Bf[ni >> 1][(ni & 1) * 2 + 1];
                #pragma unroll
                for (int mi = 0; mi < 4; mi++)
                    mma16816(acc[mi][ni], Ax[mi], b0, b1);
            }
        }
    }

    // ---- epilogue: Yat transform from register accumulators ----
    const int g  = lane >> 2;
    const int tg = lane & 3;
    const float a = *alpha;
    const float basev = sqrtf((float)NDIM) / logf(1.0f + (float)NDIM);
    const float scale = powf(basev, a);

    #pragma unroll
    for (int mi = 0; mi < 4; mi++) {
        const int r0 = m0 + wm * 64 + mi * 16 + g;
        const float xs0 = g_x_sq[r0];
        const float xs1 = g_x_sq[r0 + 8];
        #pragma unroll
        for (int ni = 0; ni < 4; ni++) {
            const int col = n0 + wn * 32 + ni * 8 + tg * 2;
            const float ws0 = __ldg(&g_w_sq[col]);
            const float ws1 = __ldg(&g_w_sq[col + 1]);
            const float bi0 = __ldg(&bias[col]);
            const float bi1 = __ldg(&bias[col + 1]);
            float y;
            float2 o;
            y = acc[mi][ni][0];
            o.x = scale * y * y / (xs0 + ws0 - 2.0f * y + EPSV) + bi0;
            y = acc[mi][ni][1];
            o.y = scale * y * y / (xs0 + ws1 - 2.0f * y + EPSV) + bi1;
            *reinterpret_cast<float2*>(out + (size_t)r0 * NDIM + col) = o;
            y = acc[mi][ni][2];
            o.x = scale * y * y / (xs1 + ws0 - 2.0f * y + EPSV) + bi0;
            y = acc[mi][ni][3];
            o.y = scale * y * y / (xs1 + ws1 - 2.0f * y + EPSV) + bi1;
            *reinterpret_cast<float2*>(out + (size_t)(r0 + 8) * NDIM + col) = o;
        }
    }
}

// ---------------- launch ----------------
extern "C" void kernel_launch(void* const* d_in, const int* in_sizes, int n_in,
                              void* d_out, int out_size) {
    (void)in_sizes; (void)n_in; (void)out_size;
    const float* x     = (const float*)d_in[0];
    const float* w     = (const float*)d_in[1];
    const float* alpha = (const float*)d_in[2];
    const float* bias  = (const float*)d_in[3];
    float* out = (float*)d_out;

    cudaFuncSetAttribute(yat_gemm, cudaFuncAttributeMaxDynamicSharedMemorySize, SMEM_BYTES);

    split_kernel<<<MDIM + NDIM, 256>>>(x, w);
    yat_gemm<<<(MDIM / TM) * (NDIM / TN), 256, SMEM_BYTES>>>(out, alpha, bias);
}

// round 15
// speedup vs baseline: 7.3406x; 1.5584x over previous
#include <cuda_runtime.h>
#include <cuda_fp16.h>
#include <stdint.h>
#include <math.h>

// ---------------- problem constants ----------------
#define MDIM 16384      // B*S
#define NDIM 2048       // F
#define KDIM 2048       // D
#define TM   128        // CTA tile M
#define TN   128        // CTA tile N
#define TKC  64         // K (halves) per pipeline stage (4 k16 MMA steps)
#define KITERS (KDIM/TKC)   // 32
#define EPSV 1e-6f

// SMEM per stage: A (x fp16) | B (w fp16); 128 rows x 128B, padded to 144B
#define ROWB   144
#define A_OFF  0
#define B_OFF  (128*ROWB)        // 18432
#define STAGE_BYTES (2*128*ROWB) // 36864
#define NSTAGE 2
#define SMEM_BYTES (NSTAGE*STAGE_BYTES)   // 73728 -> 3 CTAs/SM

// ---------------- scratch ----------------
__device__ __half g_x_h[33554432];
__device__ __half g_w_h[4194304];
__device__ float  g_x_sq[MDIM];
__device__ float  g_w_sq[NDIM];

// ---------------- PTX helpers ----------------
__device__ __forceinline__ uint32_t smem_u32(const void* p) {
    uint32_t r;
    asm("{ .reg .u64 t; cvta.to.shared.u64 t, %1; cvt.u32.u64 %0, t; }" : "=r"(r) : "l"(p));
    return r;
}
__device__ __forceinline__ void cp16(uint32_t dst, const void* src) {
    asm volatile("cp.async.cg.shared.global [%0], [%1], 16;" :: "r"(dst), "l"(src) : "memory");
}
__device__ __forceinline__ void cp_commit() {
    asm volatile("cp.async.commit_group;" ::: "memory");
}
template <int N>
__device__ __forceinline__ void cp_wait() {
    asm volatile("cp.async.wait_group %0;" :: "n"(N) : "memory");
}
__device__ __forceinline__ void ldsm4(uint32_t* r, uint32_t addr) {
    asm volatile("ldmatrix.sync.aligned.m8n8.x4.shared.b16 {%0,%1,%2,%3}, [%4];"
        : "=r"(r[0]), "=r"(r[1]), "=r"(r[2]), "=r"(r[3]) : "r"(addr));
}
// m16n8k16 row.col f16 -> f32
__device__ __forceinline__ void mma16816(float* c, const uint32_t* a, uint32_t b0, uint32_t b1) {
    asm volatile(
        "mma.sync.aligned.m16n8k16.row.col.f32.f16.f16.f32 "
        "{%0,%1,%2,%3}, {%4,%5,%6,%7}, {%8,%9}, {%0,%1,%2,%3};"
        : "+f"(c[0]), "+f"(c[1]), "+f"(c[2]), "+f"(c[3])
        : "r"(a[0]), "r"(a[1]), "r"(a[2]), "r"(a[3]), "r"(b0), "r"(b1));
}

// ---------------- pre-pass: fp32 -> fp16 + exact row sum-of-squares ----------------
__global__ __launch_bounds__(256) void split_kernel(const float* __restrict__ x,
                                                    const float* __restrict__ w) {
    int row = blockIdx.x;
    const int tid = threadIdx.x;
    const float* src;
    __half* dst;
    float* sq;
    if (row < MDIM) {
        src = x + (size_t)row * KDIM;
        dst = g_x_h + (size_t)row * KDIM;
        sq = g_x_sq + row;
    } else {
        int r = row - MDIM;
        src = w + (size_t)r * KDIM;
        dst = g_w_h + (size_t)r * KDIM;
        sq = g_w_sq + r;
    }
    float acc = 0.f;
    #pragma unroll
    for (int half = 0; half < 2; half++) {
        int j = tid * 4 + half * 1024;
        float4 v = *reinterpret_cast<const float4*>(src + j);
        __half h0 = __float2half_rn(v.x), h1 = __float2half_rn(v.y);
        __half h2 = __float2half_rn(v.z), h3 = __float2half_rn(v.w);
        *reinterpret_cast<__half2*>(dst + j)     = __halves2half2(h0, h1);
        *reinterpret_cast<__half2*>(dst + j + 2) = __halves2half2(h2, h3);
        acc += v.x*v.x + v.y*v.y + v.z*v.z + v.w*v.w;
    }
    __shared__ float red[8];
    #pragma unroll
    for (int o = 16; o > 0; o >>= 1) acc += __shfl_xor_sync(0xffffffffu, acc, o);
    if ((tid & 31) == 0) red[tid >> 5] = acc;
    __syncthreads();
    if (tid < 8) {
        float v = red[tid];
        #pragma unroll
        for (int o = 4; o > 0; o >>= 1) v += __shfl_xor_sync(0xffu, v, o);
        if (tid == 0) *sq = v;
    }
}

// ---------------- main GEMM + Yat epilogue ----------------
// grid = 2048 (128 mtiles x 16 ntiles), block = 128 (4 warps: 2 M x 2 N, warp tile 64x64)
// single-pass fp16 x fp16 -> fp32 acc, TKC=64, 2-stage double buffer, 3 CTAs/SM.
__global__ __launch_bounds__(128, 3) void yat_gemm(float* __restrict__ out,
                                                   const float* __restrict__ alpha,
                                                   const float* __restrict__ bias) {
    extern __shared__ char smem[];
    const uint32_t smem_base = smem_u32(smem);

    const int tid = threadIdx.x;
    const int mtile = blockIdx.x >> 4;
    const int ntile = blockIdx.x & 15;
    const int m0 = mtile * TM;
    const int n0 = ntile * TN;

    const __half* xh = g_x_h + (size_t)m0 * KDIM;
    const __half* wh = g_w_h + (size_t)n0 * KDIM;

    // ---- stage loader: 2 planes x 128 rows x 128B = 1024 chunks/plane, 16 cp/thread ----
    auto load_stage = [&](int i) {
        const uint32_t sb = smem_base + (uint32_t)(i & 1) * STAGE_BYTES;
        const int kk = i * TKC;
        #pragma unroll
        for (int it = 0; it < 8; it++) {
            int q = tid + 128 * it;              // 0..1023
            int r = q >> 3, c = q & 7;
            uint32_t so = (uint32_t)r * ROWB + (uint32_t)c * 16;
            size_t go = (size_t)r * KDIM + kk + c * 8;
            cp16(sb + A_OFF + so, xh + go);
            cp16(sb + B_OFF + so, wh + go);
        }
    };

    // ---- warp/lane geometry: 4 warps, warp tile 64x64 ----
    const int warp = tid >> 5;
    const int lane = tid & 31;
    const int wm = warp & 1;        // 2 warps along M (64 rows each)
    const int wn = warp >> 1;       // 2 warps along N (64 cols each)

    const uint32_t a_loff = (uint32_t)(wm * 64 + (lane & 15)) * ROWB
                          + (uint32_t)(lane >> 4) * 16;
    const uint32_t b_loff = (uint32_t)(wn * 64 + (lane & 7) + ((lane >> 4) & 1) * 8) * ROWB
                          + (uint32_t)((lane >> 3) & 1) * 16;

    float acc[4][8][4];   // 4 m16-blocks x 8 n8-blocks x 4 elems = 128 regs
    #pragma unroll
    for (int mi = 0; mi < 4; mi++)
        #pragma unroll
        for (int ni = 0; ni < 8; ni++)
            #pragma unroll
            for (int e = 0; e < 4; e++) acc[mi][ni][e] = 0.f;

    load_stage(0); cp_commit();

    for (int i = 0; i < KITERS; i++) {
        cp_wait<0>();
        __syncthreads();           // stage i resident AND all warps done reading stage i-1
        if (i + 1 < KITERS) { load_stage(i + 1); cp_commit(); }

        const uint32_t sb = smem_base + (uint32_t)(i & 1) * STAGE_BYTES;
        const uint32_t aA = sb + A_OFF + a_loff;
        const uint32_t aB = sb + B_OFF + b_loff;

        #pragma unroll
        for (int ks = 0; ks < 4; ks++) {
            const uint32_t kb = (uint32_t)ks * 32;    // 16 halves per k-step
            uint32_t Ax[4][4];
            #pragma unroll
            for (int mi = 0; mi < 4; mi++)
                ldsm4(Ax[mi], aA + (uint32_t)mi * (16 * ROWB) + kb);
            #pragma unroll
            for (int j = 0; j < 4; j++) {             // 4 n16-groups
                uint32_t Bf[4];
                ldsm4(Bf, aB + (uint32_t)j * (16 * ROWB) + kb);
                #pragma unroll
                for (int ns = 0; ns < 2; ns++) {
                    uint32_t b0 = Bf[ns * 2];
                    uint32_t b1 = Bf[ns * 2 + 1];
                    #pragma unroll
                    for (int mi = 0; mi < 4; mi++)
                        mma16816(acc[mi][j * 2 + ns], Ax[mi], b0, b1);
                }
            }
        }
    }

    // ---- epilogue: Yat transform from register accumulators ----
    const int g  = lane >> 2;
    const int tg = lane & 3;
    const float a = *alpha;
    const float basev = sqrtf((float)NDIM) / logf(1.0f + (float)NDIM);
    const float scale = powf(basev, a);

    #pragma unroll
    for (int mi = 0; mi < 4; mi++) {
        const int r0 = m0 + wm * 64 + mi * 16 + g;
        const float xs0 = g_x_sq[r0];
        const float xs1 = g_x_sq[r0 + 8];
        #pragma unroll
        for (int ni = 0; ni < 8; ni++) {
            const int col = n0 + wn * 64 + ni * 8 + tg * 2;
            const float ws0 = __ldg(&g_w_sq[col]);
            const float ws1 = __ldg(&g_w_sq[col + 1]);
            const float bi0 = __ldg(&bias[col]);
            const float bi1 = __ldg(&bias[col + 1]);
            float y;
            float2 o;
            y = acc[mi][ni][0];
            o.x = scale * y * y / (xs0 + ws0 - 2.0f * y + EPSV) + bi0;
            y = acc[mi][ni][1];
            o.y = scale * y * y / (xs0 + ws1 - 2.0f * y + EPSV) + bi1;
            *reinterpret_cast<float2*>(out + (size_t)r0 * NDIM + col) = o;
            y = acc[mi][ni][2];
            o.x = scale * y * y / (xs1 + ws0 - 2.0f * y + EPSV) + bi0;
            y = acc[mi][ni][3];
            o.y = scale * y * y / (xs1 + ws1 - 2.0f * y + EPSV) + bi1;
            *reinterpret_cast<float2*>(out + (size_t)(r0 + 8) * NDIM + col) = o;
        }
    }
}

// ---------------- launch ----------------
extern "C" void kernel_launch(void* const* d_in, const int* in_sizes, int n_in,
                              void* d_out, int out_size) {
    (void)in_sizes; (void)n_in; (void)out_size;
    const float* x     = (const float*)d_in[0];
    const float* w     = (const float*)d_in[1];
    const float* alpha = (const float*)d_in[2];
    const float* bias  = (const float*)d_in[3];
    float* out = (float*)d_out;

    cudaFuncSetAttribute(yat_gemm, cudaFuncAttributeMaxDynamicSharedMemorySize, SMEM_BYTES);

    split_kernel<<<MDIM + NDIM, 256>>>(x, w);
    yat_gemm<<<(MDIM / TM) * (NDIM / TN), 128, SMEM_BYTES>>>(out, alpha, bias);
}

// round 17
// speedup vs baseline: 7.5255x; 1.0252x over previous
#include <cuda_runtime.h>
#include <cuda_fp16.h>
#include <stdint.h>
#include <math.h>

// ---------------- problem constants ----------------
#define MDIM 16384      // B*S
#define NDIM 2048       // F
#define KDIM 2048       // D
#define TM   128        // CTA tile M
#define TN   128        // CTA tile N
#define TKC  64         // K (halves) per pipeline stage (4 k16 MMA steps)
#define KITERS (KDIM/TKC)   // 32
#define EPSV 1e-6f

// SMEM per stage: A (x fp16) | B (w fp16); 128 rows x 128B, padded to 144B
#define ROWB   144
#define A_OFF  0
#define B_OFF  (128*ROWB)        // 18432
#define STAGE_BYTES (2*128*ROWB) // 36864
#define NSTAGE 2
#define SMEM_BYTES (NSTAGE*STAGE_BYTES)   // 73728 -> 3 CTAs/SM

// ---------------- scratch ----------------
__device__ __half g_x_h[33554432];
__device__ __half g_w_h[4194304];
__device__ float  g_x_sq[MDIM];
__device__ float  g_w_sq[NDIM];

// ---------------- PTX helpers ----------------
__device__ __forceinline__ uint32_t smem_u32(const void* p) {
    uint32_t r;
    asm("{ .reg .u64 t; cvta.to.shared.u64 t, %1; cvt.u32.u64 %0, t; }" : "=r"(r) : "l"(p));
    return r;
}
__device__ __forceinline__ void cp16(uint32_t dst, const void* src) {
    asm volatile("cp.async.cg.shared.global [%0], [%1], 16;" :: "r"(dst), "l"(src) : "memory");
}
__device__ __forceinline__ void cp_commit() {
    asm volatile("cp.async.commit_group;" ::: "memory");
}
template <int N>
__device__ __forceinline__ void cp_wait() {
    asm volatile("cp.async.wait_group %0;" :: "n"(N) : "memory");
}
__device__ __forceinline__ void ldsm4(uint32_t* r, uint32_t addr) {
    asm volatile("ldmatrix.sync.aligned.m8n8.x4.shared.b16 {%0,%1,%2,%3}, [%4];"
        : "=r"(r[0]), "=r"(r[1]), "=r"(r[2]), "=r"(r[3]) : "r"(addr));
}
// m16n8k16 row.col f16 -> f32
__device__ __forceinline__ void mma16816(float* c, const uint32_t* a, uint32_t b0, uint32_t b1) {
    asm volatile(
        "mma.sync.aligned.m16n8k16.row.col.f32.f16.f16.f32 "
        "{%0,%1,%2,%3}, {%4,%5,%6,%7}, {%8,%9}, {%0,%1,%2,%3};"
        : "+f"(c[0]), "+f"(c[1]), "+f"(c[2]), "+f"(c[3])
        : "r"(a[0]), "r"(a[1]), "r"(a[2]), "r"(a[3]), "r"(b0), "r"(b1));
}

// ---------------- pre-pass: fp32 -> fp16 + exact row sum-of-squares ----------------
__global__ __launch_bounds__(256) void split_kernel(const float* __restrict__ x,
                                                    const float* __restrict__ w) {
    int row = blockIdx.x;
    const int tid = threadIdx.x;
    const float* src;
    __half* dst;
    float* sq;
    if (row < MDIM) {
        src = x + (size_t)row * KDIM;
        dst = g_x_h + (size_t)row * KDIM;
        sq = g_x_sq + row;
    } else {
        int r = row - MDIM;
        src = w + (size_t)r * KDIM;
        dst = g_w_h + (size_t)r * KDIM;
        sq = g_w_sq + r;
    }
    float acc = 0.f;
    #pragma unroll
    for (int half = 0; half < 2; half++) {
        int j = tid * 4 + half * 1024;
        float4 v = *reinterpret_cast<const float4*>(src + j);
        __half h0 = __float2half_rn(v.x), h1 = __float2half_rn(v.y);
        __half h2 = __float2half_rn(v.z), h3 = __float2half_rn(v.w);
        *reinterpret_cast<__half2*>(dst + j)     = __halves2half2(h0, h1);
        *reinterpret_cast<__half2*>(dst + j + 2) = __halves2half2(h2, h3);
        acc += v.x*v.x + v.y*v.y + v.z*v.z + v.w*v.w;
    }
    __shared__ float red[8];
    #pragma unroll
    for (int o = 16; o > 0; o >>= 1) acc += __shfl_xor_sync(0xffffffffu, acc, o);
    if ((tid & 31) == 0) red[tid >> 5] = acc;
    __syncthreads();
    if (tid < 8) {
        float v = red[tid];
        #pragma unroll
        for (int o = 4; o > 0; o >>= 1) v += __shfl_xor_sync(0xffu, v, o);
        if (tid == 0) *sq = v;
    }
}

// ---------------- main GEMM + Yat epilogue ----------------
// grid = 2048 (128 mtiles x 16 ntiles), block = 128 (4 warps: 2 M x 2 N, warp tile 64x64)
// single-pass fp16 x fp16 -> fp32 acc, TKC=64, 2-stage double buffer, 3 CTAs/SM.
// Inner k-step software-pipelines B-fragment ldsm against the MMA runs.
__global__ __launch_bounds__(128, 3) void yat_gemm(float* __restrict__ out,
                                                   const float* __restrict__ alpha,
                                                   const float* __restrict__ bias) {
    extern __shared__ char smem[];
    const uint32_t smem_base = smem_u32(smem);

    const int tid = threadIdx.x;
    const int mtile = blockIdx.x >> 4;
    const int ntile = blockIdx.x & 15;
    const int m0 = mtile * TM;
    const int n0 = ntile * TN;

    const __half* xh = g_x_h + (size_t)m0 * KDIM;
    const __half* wh = g_w_h + (size_t)n0 * KDIM;

    // ---- stage loader: 2 planes x 128 rows x 128B = 1024 chunks/plane, 16 cp/thread ----
    auto load_stage = [&](int i) {
        const uint32_t sb = smem_base + (uint32_t)(i & 1) * STAGE_BYTES;
        const int kk = i * TKC;
        #pragma unroll
        for (int it = 0; it < 8; it++) {
            int q = tid + 128 * it;              // 0..1023
            int r = q >> 3, c = q & 7;
            uint32_t so = (uint32_t)r * ROWB + (uint32_t)c * 16;
            size_t go = (size_t)r * KDIM + kk + c * 8;
            cp16(sb + A_OFF + so, xh + go);
            cp16(sb + B_OFF + so, wh + go);
        }
    };

    // ---- warp/lane geometry: 4 warps, warp tile 64x64 ----
    const int warp = tid >> 5;
    const int lane = tid & 31;
    const int wm = warp & 1;        // 2 warps along M (64 rows each)
    const int wn = warp >> 1;       // 2 warps along N (64 cols each)

    const uint32_t a_loff = (uint32_t)(wm * 64 + (lane & 15)) * ROWB
                          + (uint32_t)(lane >> 4) * 16;
    const uint32_t b_loff = (uint32_t)(wn * 64 + (lane & 7) + ((lane >> 4) & 1) * 8) * ROWB
                          + (uint32_t)((lane >> 3) & 1) * 16;

    float acc[4][8][4];   // 4 m16-blocks x 8 n8-blocks x 4 elems = 128 regs
    #pragma unroll
    for (int mi = 0; mi < 4; mi++)
        #pragma unroll
        for (int ni = 0; ni < 8; ni++)
            #pragma unroll
            for (int e = 0; e < 4; e++) acc[mi][ni][e] = 0.f;

    load_stage(0); cp_commit();

    for (int i = 0; i < KITERS; i++) {
        cp_wait<0>();
        __syncthreads();           // stage i resident AND all warps done reading stage i-1
        if (i + 1 < KITERS) { load_stage(i + 1); cp_commit(); }

        const uint32_t sb = smem_base + (uint32_t)(i & 1) * STAGE_BYTES;
        const uint32_t aA = sb + A_OFF + a_loff;
        const uint32_t aB = sb + B_OFF + b_loff;

        #pragma unroll
        for (int ks = 0; ks < 4; ks++) {
            const uint32_t kb = (uint32_t)ks * 32;    // 16 halves per k-step
            uint32_t Ax[4][4];
            #pragma unroll
            for (int mi = 0; mi < 4; mi++)
                ldsm4(Ax[mi], aA + (uint32_t)mi * (16 * ROWB) + kb);
            // B double buffer: issue ldsm for group j+1 BEFORE the MMAs of group j
            uint32_t Bf[2][4];
            ldsm4(Bf[0], aB + kb);
            #pragma unroll
            for (int j = 0; j < 4; j++) {             // 4 n16-groups
                if (j < 3)
                    ldsm4(Bf[(j + 1) & 1], aB + (uint32_t)(j + 1) * (16 * ROWB) + kb);
                uint32_t* Bc = Bf[j & 1];
                #pragma unroll
                for (int ns = 0; ns < 2; ns++) {
                    uint32_t b0 = Bc[ns * 2];
                    uint32_t b1 = Bc[ns * 2 + 1];
                    #pragma unroll
                    for (int mi = 0; mi < 4; mi++)
                        mma16816(acc[mi][j * 2 + ns], Ax[mi], b0, b1);
                }
            }
        }
    }

    // ---- epilogue: Yat transform from register accumulators ----
    const int g  = lane >> 2;
    const int tg = lane & 3;
    const float a = *alpha;
    const float basev = sqrtf((float)NDIM) / logf(1.0f + (float)NDIM);
    const float scale = powf(basev, a);

    #pragma unroll
    for (int mi = 0; mi < 4; mi++) {
        const int r0 = m0 + wm * 64 + mi * 16 + g;
        const float xs0 = g_x_sq[r0];
        const float xs1 = g_x_sq[r0 + 8];
        #pragma unroll
        for (int ni = 0; ni < 8; ni++) {
            const int col = n0 + wn * 64 + ni * 8 + tg * 2;
            const float ws0 = __ldg(&g_w_sq[col]);
            const float ws1 = __ldg(&g_w_sq[col + 1]);
            const float bi0 = __ldg(&bias[col]);
            const float bi1 = __ldg(&bias[col + 1]);
            float y;
            float2 o;
            y = acc[mi][ni][0];
            o.x = scale * y * y / (xs0 + ws0 - 2.0f * y + EPSV) + bi0;
            y = acc[mi][ni][1];
            o.y = scale * y * y / (xs0 + ws1 - 2.0f * y + EPSV) + bi1;
            *reinterpret_cast<float2*>(out + (size_t)r0 * NDIM + col) = o;
            y = acc[mi][ni][2];
            o.x = scale * y * y / (xs1 + ws0 - 2.0f * y + EPSV) + bi0;
            y = acc[mi][ni][3];
            o.y = scale * y * y / (xs1 + ws1 - 2.0f * y + EPSV) + bi1;
            *reinterpret_cast<float2*>(out + (size_t)(r0 + 8) * NDIM + col) = o;
        }
    }
}

// ---------------- launch ----------------
extern "C" void kernel_launch(void* const* d_in, const int* in_sizes, int n_in,
                              void* d_out, int out_size) {
    (void)in_sizes; (void)n_in; (void)out_size;
    const float* x     = (const float*)d_in[0];
    const float* w     = (const float*)d_in[1];
    const float* alpha = (const float*)d_in[2];
    const float* bias  = (const float*)d_in[3];
    float* out = (float*)d_out;

    cudaFuncSetAttribute(yat_gemm, cudaFuncAttributeMaxDynamicSharedMemorySize, SMEM_BYTES);

    split_kernel<<<MDIM + NDIM, 256>>>(x, w);
    yat_gemm<<<(MDIM / TM) * (NDIM / TN), 128, SMEM_BYTES>>>(out, alpha, bias);
}